// round 1
// baseline (speedup 1.0000x reference)
#include <cuda_runtime.h>
#include <math.h>

// ---------------------------------------------------------------------------
// Problem constants
// ---------------------------------------------------------------------------
#define DIMV 512
#define BV   16
#define LV   2048
#define NROWS (BV * LV)      // 32768
#define HIDV 2048
#define GHID 128
#define LN_EPS 1e-5f

// ---------------------------------------------------------------------------
// Scratch (device globals — no allocations allowed)
// ---------------------------------------------------------------------------
__device__ float g_hln   [(size_t)NROWS * DIMV];   // LN1 output  [n][d]
__device__ float g_mixg  [(size_t)NROWS * DIMV];   // gelu(avg conv) [n][c]
__device__ float g_mixed2[(size_t)NROWS * DIMV];   // after wmix GEMM [n][o]
__device__ float g_x1    [(size_t)NROWS * DIMV];   // after first residual
__device__ float g_h2    [(size_t)NROWS * DIMV];   // LN2 output
__device__ float g_hid   [(size_t)NROWS * HIDV];   // FFN hidden
__device__ float g_ct    [BV * DIMV];              // channel token
__device__ float g_gate  [BV * DIMV];              // sigmoid gate
__device__ float g_wmixT [DIMV * DIMV];            // wmix transposed [c][o]

// ---------------------------------------------------------------------------
// Helpers
// ---------------------------------------------------------------------------
__device__ __forceinline__ float gelu_f(float v) {
    return 0.5f * v * (1.0f + erff(v * 0.70710678118654752f));
}

// block reduce for 128 threads: sum + sumsq
__device__ __forceinline__ void block_reduce_2(float& s, float& sq) {
    #pragma unroll
    for (int off = 16; off > 0; off >>= 1) {
        s  += __shfl_down_sync(0xffffffffu, s,  off);
        sq += __shfl_down_sync(0xffffffffu, sq, off);
    }
    __shared__ float sh[8];
    int w = threadIdx.x >> 5, lane = threadIdx.x & 31;
    if (lane == 0) { sh[w] = s; sh[4 + w] = sq; }
    __syncthreads();
    if (threadIdx.x < 32) {
        float a  = (lane < 4) ? sh[lane] : 0.f;
        float b  = (lane < 4) ? sh[4 + lane] : 0.f;
        #pragma unroll
        for (int off = 2; off > 0; off >>= 1) {
            a += __shfl_down_sync(0xffffffffu, a, off);
            b += __shfl_down_sync(0xffffffffu, b, off);
        }
        if (lane == 0) { sh[0] = a; sh[1] = b; }
    }
    __syncthreads();
    s = sh[0]; sq = sh[1];
}

// ---------------------------------------------------------------------------
// LayerNorm over last dim (512). One block (128 thr) per row; float4 per thread.
// ---------------------------------------------------------------------------
__global__ void ln_kernel(const float* __restrict__ x, const float* __restrict__ g,
                          const float* __restrict__ b, float* __restrict__ out) {
    size_t row = blockIdx.x;
    const float4* xr = (const float4*)(x + row * DIMV);
    float4 v = xr[threadIdx.x];
    float s  = v.x + v.y + v.z + v.w;
    float sq = v.x * v.x + v.y * v.y + v.z * v.z + v.w * v.w;
    block_reduce_2(s, sq);
    float mu  = s * (1.0f / DIMV);
    float var = sq * (1.0f / DIMV) - mu * mu;
    float r   = rsqrtf(var + LN_EPS);
    float4 gg = ((const float4*)g)[threadIdx.x];
    float4 bb = ((const float4*)b)[threadIdx.x];
    float4 o;
    o.x = (v.x - mu) * r * gg.x + bb.x;
    o.y = (v.y - mu) * r * gg.y + bb.y;
    o.z = (v.z - mu) * r * gg.z + bb.z;
    o.w = (v.w - mu) * r * gg.w + bb.w;
    ((float4*)(out + row * DIMV))[threadIdx.x] = o;
}

// ---------------------------------------------------------------------------
// Fused depthwise conv (k=3,5,7 averaged) + GELU.
// Input g_hln laid out [b][l][c]; conv along l (stride DIMV).
// XLA conv = cross-correlation (no kernel flip): y[l] = sum_t h[l+t-pad]*w[t].
// ---------------------------------------------------------------------------
__global__ void conv_gelu_kernel(const float* __restrict__ h,
                                 const float* __restrict__ w3, const float* __restrict__ b3,
                                 const float* __restrict__ w5, const float* __restrict__ b5,
                                 const float* __restrict__ w7, const float* __restrict__ b7,
                                 float* __restrict__ out) {
    size_t idx = (size_t)blockIdx.x * blockDim.x + threadIdx.x;   // over NROWS*DIMV
    int c = (int)(idx & (DIMV - 1));
    size_t n = idx >> 9;
    int l = (int)(n & (LV - 1));
    size_t bb = n >> 11;

    float taps[7];
    #pragma unroll
    for (int j = 0; j < 7; j++) taps[j] = w7[c * 7 + j];
    #pragma unroll
    for (int j = 1; j <= 5; j++) taps[j] += w5[c * 5 + (j - 1)];
    #pragma unroll
    for (int j = 2; j <= 4; j++) taps[j] += w3[c * 3 + (j - 2)];

    float acc = b3[c] + b5[c] + b7[c];
    const float* base = h + (bb * LV) * DIMV + c;
    #pragma unroll
    for (int j = 0; j < 7; j++) {
        int ll = l + j - 3;
        if (ll >= 0 && ll < LV)
            acc += taps[j] * base[(size_t)ll * DIMV];
    }
    acc *= (1.0f / 3.0f);
    out[idx] = gelu_f(acc);
}

// ---------------------------------------------------------------------------
// 512x512 transpose of wmix:  g_wmixT[c][o] = wmix[o][c]
// ---------------------------------------------------------------------------
__global__ void transpose512_kernel(const float* __restrict__ in, float* __restrict__ out) {
    __shared__ float tile[32][33];
    int x = blockIdx.x * 32 + threadIdx.x;
    int y = blockIdx.y * 32 + threadIdx.y;
    #pragma unroll
    for (int i = 0; i < 32; i += 8)
        tile[threadIdx.y + i][threadIdx.x] = in[(size_t)(y + i) * DIMV + x];
    __syncthreads();
    x = blockIdx.y * 32 + threadIdx.x;
    y = blockIdx.x * 32 + threadIdx.y;
    #pragma unroll
    for (int i = 0; i < 32; i += 8)
        out[(size_t)(y + i) * DIMV + x] = tile[threadIdx.x][threadIdx.y + i];
}

// ---------------------------------------------------------------------------
// channel_token[b][o] = mean over l of mixed2[b][l][o]
// ---------------------------------------------------------------------------
__global__ void ct_kernel(const float* __restrict__ m2, float* __restrict__ ct) {
    int b = blockIdx.y;
    int o = blockIdx.x * 256 + threadIdx.x;
    const float* p = m2 + ((size_t)b * LV) * DIMV + o;
    float s = 0.f;
    #pragma unroll 8
    for (int l = 0; l < LV; l++) s += p[(size_t)l * DIMV];
    ct[b * DIMV + o] = s * (1.0f / LV);
}

// ---------------------------------------------------------------------------
// gate[b] = sigmoid(gelu(ct[b] @ cg_w1 + cg_b1) @ cg_w2 + cg_b2)
// one block (128 thr) per batch element
// ---------------------------------------------------------------------------
__global__ void gate_kernel(const float* __restrict__ ct,
                            const float* __restrict__ w1, const float* __restrict__ b1,
                            const float* __restrict__ w2, const float* __restrict__ b2,
                            float* __restrict__ gate) {
    __shared__ float sct[DIMV];
    __shared__ float shid[GHID];
    int b = blockIdx.x, t = threadIdx.x;
    for (int i = t; i < DIMV; i += 128) sct[i] = ct[b * DIMV + i];
    __syncthreads();
    float acc = b1[t];
    #pragma unroll 8
    for (int d = 0; d < DIMV; d++) acc += sct[d] * w1[d * GHID + t];
    shid[t] = gelu_f(acc);
    __syncthreads();
    for (int o = t; o < DIMV; o += 128) {
        float a2 = b2[o];
        #pragma unroll 8
        for (int g = 0; g < GHID; g++) a2 += shid[g] * w2[g * DIMV + o];
        gate[b * DIMV + o] = 1.0f / (1.0f + expf(-a2));
    }
}

// ---------------------------------------------------------------------------
// SGEMM: C[n][m] = epilogue( sum_k A'[n][k] * W[k][m] )
//   A' = A, or A * gate[b(n)][k] when GATE (K==512 in that case)
//   EPI 0: + bias[m]
//   EPI 1: gelu(+ bias[m])
//   EPI 2: resid[n][m] + (+ bias[m]) * ls[m]      (M==512 for this mode)
// BM=128 BN=128 BK=16, 256 threads, 8x8 per thread.
// Dims assumed: Nrows % 128 == 0, K % 16 == 0, M % 128 == 0 (true here).
// ---------------------------------------------------------------------------
template<bool GATE, int EPI>
__global__ void gemm_kernel(const float* __restrict__ A, const float* __restrict__ W,
                            const float* __restrict__ bias, float* __restrict__ C,
                            int K, int M,
                            const float* __restrict__ gate,
                            const float* __restrict__ resid,
                            const float* __restrict__ ls) {
    const int BM = 128, BN = 128, BK = 16;
    __shared__ float As[BK][BM];
    __shared__ float Bs[BK][BN];

    int tid = threadIdx.x;
    size_t rowBase = (size_t)blockIdx.y * BM;
    int colBase = blockIdx.x * BN;

    int aRow = tid >> 2;            // 0..63  (+64 for second half)
    int aCol = (tid & 3) * 4;       // 0,4,8,12
    int wRow = tid >> 5;            // 0..7   (+8 for second half)
    int wCol = (tid & 31) * 4;

    int ty = tid >> 4;              // 0..15 -> row group
    int tx = tid & 15;              // 0..15 -> col group

    int b_idx = (int)(rowBase >> 11);   // batch index (L=2048 divides BM blocks evenly)

    float acc[8][8];
    #pragma unroll
    for (int i = 0; i < 8; i++)
        #pragma unroll
        for (int j = 0; j < 8; j++) acc[i][j] = 0.f;

    for (int k0 = 0; k0 < K; k0 += BK) {
        // ---- load A tile (BM x BK), store transposed ----
        #pragma unroll
        for (int i = 0; i < 2; i++) {
            int r = aRow + i * 64;
            float4 v = *(const float4*)&A[(rowBase + r) * (size_t)K + k0 + aCol];
            if (GATE) {
                const float* gp = &gate[b_idx * K + k0 + aCol];
                v.x *= gp[0]; v.y *= gp[1]; v.z *= gp[2]; v.w *= gp[3];
            }
            As[aCol + 0][r] = v.x;
            As[aCol + 1][r] = v.y;
            As[aCol + 2][r] = v.z;
            As[aCol + 3][r] = v.w;
        }
        // ---- load W tile (BK x BN) ----
        #pragma unroll
        for (int i = 0; i < 2; i++) {
            int r = wRow + i * 8;
            float4 v = *(const float4*)&W[(size_t)(k0 + r) * M + colBase + wCol];
            *(float4*)&Bs[r][wCol] = v;
        }
        __syncthreads();

        #pragma unroll
        for (int kk = 0; kk < BK; kk++) {
            float4 a0 = *(const float4*)&As[kk][ty * 8];
            float4 a1 = *(const float4*)&As[kk][ty * 8 + 4];
            float4 b0 = *(const float4*)&Bs[kk][tx * 8];
            float4 b1 = *(const float4*)&Bs[kk][tx * 8 + 4];
            float ra[8] = {a0.x, a0.y, a0.z, a0.w, a1.x, a1.y, a1.z, a1.w};
            float rb[8] = {b0.x, b0.y, b0.z, b0.w, b1.x, b1.y, b1.z, b1.w};
            #pragma unroll
            for (int i = 0; i < 8; i++)
                #pragma unroll
                for (int j = 0; j < 8; j++)
                    acc[i][j] = fmaf(ra[i], rb[j], acc[i][j]);
        }
        __syncthreads();
    }

    // ---- epilogue ----
    float bres[8], lsv[8];
    #pragma unroll
    for (int j = 0; j < 8; j++) {
        bres[j] = bias[colBase + tx * 8 + j];
        if (EPI == 2) lsv[j] = ls[colBase + tx * 8 + j];
    }
    #pragma unroll
    for (int i = 0; i < 8; i++) {
        size_t n = rowBase + ty * 8 + i;
        float* cp = C + n * (size_t)M + colBase + tx * 8;
        float vres[8];
        if (EPI == 2) {
            const float* rp = resid + n * (size_t)M + colBase + tx * 8;
            float4 r0 = *(const float4*)rp;
            float4 r1 = *(const float4*)(rp + 4);
            vres[0] = r0.x; vres[1] = r0.y; vres[2] = r0.z; vres[3] = r0.w;
            vres[4] = r1.x; vres[5] = r1.y; vres[6] = r1.z; vres[7] = r1.w;
        }
        float o[8];
        #pragma unroll
        for (int j = 0; j < 8; j++) {
            float v = acc[i][j] + bres[j];
            if (EPI == 1) v = gelu_f(v);
            else if (EPI == 2) v = vres[j] + v * lsv[j];
            o[j] = v;
        }
        *(float4*)cp       = make_float4(o[0], o[1], o[2], o[3]);
        *(float4*)(cp + 4) = make_float4(o[4], o[5], o[6], o[7]);
    }
}

// ---------------------------------------------------------------------------
// launch
// ---------------------------------------------------------------------------
extern "C" void kernel_launch(void* const* d_in, const int* in_sizes, int n_in,
                              void* d_out, int out_size) {
    const float* x      = (const float*)d_in[0];
    const float* ln1_g  = (const float*)d_in[1];
    const float* ln1_b  = (const float*)d_in[2];
    const float* w3     = (const float*)d_in[3];
    const float* b3     = (const float*)d_in[4];
    const float* w5     = (const float*)d_in[5];
    const float* b5     = (const float*)d_in[6];
    const float* w7     = (const float*)d_in[7];
    const float* b7     = (const float*)d_in[8];
    const float* wmix   = (const float*)d_in[9];
    const float* bmix   = (const float*)d_in[10];
    const float* cg_w1  = (const float*)d_in[11];
    const float* cg_b1  = (const float*)d_in[12];
    const float* cg_w2  = (const float*)d_in[13];
    const float* cg_b2  = (const float*)d_in[14];
    const float* wout   = (const float*)d_in[15];
    const float* bout   = (const float*)d_in[16];
    const float* ls1    = (const float*)d_in[17];
    const float* ln2_g  = (const float*)d_in[18];
    const float* ln2_b  = (const float*)d_in[19];
    const float* ffn_w1 = (const float*)d_in[20];
    const float* ffn_b1 = (const float*)d_in[21];
    const float* ffn_w2 = (const float*)d_in[22];
    const float* ffn_b2 = (const float*)d_in[23];
    const float* ls2    = (const float*)d_in[24];
    float* out = (float*)d_out;

    float *p_hln, *p_mixg, *p_mixed2, *p_x1, *p_h2, *p_hid, *p_ct, *p_gate, *p_wmixT;
    cudaGetSymbolAddress((void**)&p_hln,    g_hln);
    cudaGetSymbolAddress((void**)&p_mixg,   g_mixg);
    cudaGetSymbolAddress((void**)&p_mixed2, g_mixed2);
    cudaGetSymbolAddress((void**)&p_x1,     g_x1);
    cudaGetSymbolAddress((void**)&p_h2,     g_h2);
    cudaGetSymbolAddress((void**)&p_hid,    g_hid);
    cudaGetSymbolAddress((void**)&p_ct,     g_ct);
    cudaGetSymbolAddress((void**)&p_gate,   g_gate);
    cudaGetSymbolAddress((void**)&p_wmixT,  g_wmixT);

    // 0) transpose wmix -> [c][o]
    transpose512_kernel<<<dim3(16, 16), dim3(32, 8)>>>(wmix, p_wmixT);

    // 1) LN1
    ln_kernel<<<NROWS, 128>>>(x, ln1_g, ln1_b, p_hln);

    // 2) fused depthwise convs + gelu
    conv_gelu_kernel<<<(NROWS * DIMV) / 256, 256>>>(p_hln, w3, b3, w5, b5, w7, b7, p_mixg);

    // 3) mixed2 = mixg @ wmixT + bmix
    gemm_kernel<false, 0><<<dim3(DIMV / 128, NROWS / 128), 256>>>(
        p_mixg, p_wmixT, bmix, p_mixed2, DIMV, DIMV, nullptr, nullptr, nullptr);

    // 4) channel token mean
    ct_kernel<<<dim3(2, BV), 256>>>(p_mixed2, p_ct);

    // 5) gate MLP
    gate_kernel<<<BV, 128>>>(p_ct, cg_w1, cg_b1, cg_w2, cg_b2, p_gate);

    // 6) x1 = x + ((mixed2*gate) @ wout + bout) * ls1
    gemm_kernel<true, 2><<<dim3(DIMV / 128, NROWS / 128), 256>>>(
        p_mixed2, wout, bout, p_x1, DIMV, DIMV, p_gate, x, ls1);

    // 7) LN2
    ln_kernel<<<NROWS, 128>>>(p_x1, ln2_g, ln2_b, p_h2);

    // 8) hid = gelu(h2 @ ffn_w1 + ffn_b1)
    gemm_kernel<false, 1><<<dim3(HIDV / 128, NROWS / 128), 256>>>(
        p_h2, ffn_w1, ffn_b1, p_hid, DIMV, HIDV, nullptr, nullptr, nullptr);

    // 9) out = x1 + (hid @ ffn_w2 + ffn_b2) * ls2
    gemm_kernel<false, 2><<<dim3(DIMV / 128, NROWS / 128), 256>>>(
        p_hid, ffn_w2, ffn_b2, out, HIDV, DIMV, nullptr, p_x1, ls2);
}

// round 3
// speedup vs baseline: 5.2796x; 5.2796x over previous
#include <cuda_runtime.h>
#include <cuda_bf16.h>
#include <math.h>
#include <stdint.h>

// ---------------------------------------------------------------------------
// Problem constants
// ---------------------------------------------------------------------------
#define DIMV 512
#define BV   16
#define LV   2048
#define NROWS (BV * LV)      // 32768
#define HIDV 2048
#define GHID 128
#define LN_EPS 1e-5f

// ---------------------------------------------------------------------------
// Scratch (device globals — no allocations allowed)
// ---------------------------------------------------------------------------
__device__ __nv_bfloat16 g_hln_bf   [(size_t)NROWS * DIMV];
__device__ __nv_bfloat16 g_mixg_bf  [(size_t)NROWS * DIMV];
__device__ __nv_bfloat16 g_mixed2_bf[(size_t)NROWS * DIMV];
__device__ __nv_bfloat16 g_gated_bf [(size_t)NROWS * DIMV];
__device__ __nv_bfloat16 g_h2_bf    [(size_t)NROWS * DIMV];
__device__ __nv_bfloat16 g_hid_bf   [(size_t)NROWS * HIDV];
__device__ float g_x1   [(size_t)NROWS * DIMV];
__device__ float g_ct   [BV * DIMV];
__device__ float g_gate [BV * DIMV];
__device__ __nv_bfloat16 g_wmixT_bf[DIMV * DIMV];          // [c][o]  (wmix.T)
__device__ __nv_bfloat16 g_wout_bf [DIMV * DIMV];          // [k][m] as given
__device__ __nv_bfloat16 g_w1_bf   [(size_t)DIMV * HIDV];  // [k][m] as given
__device__ __nv_bfloat16 g_w2_bf   [(size_t)HIDV * DIMV];  // [k][m] as given

// ---------------------------------------------------------------------------
// Helpers
// ---------------------------------------------------------------------------
__device__ __forceinline__ uint32_t smem_u32(const void* p) {
    uint32_t a;
    asm("{ .reg .u64 t; cvta.to.shared.u64 t, %1; cvt.u32.u64 %0, t; }" : "=r"(a) : "l"(p));
    return a;
}
__device__ __forceinline__ void cp16(void* sdst, const void* gsrc) {
    uint32_t s = smem_u32(sdst);
    asm volatile("cp.async.cg.shared.global [%0], [%1], 16;" :: "r"(s), "l"(gsrc));
}
#define CP_COMMIT() asm volatile("cp.async.commit_group;" ::: "memory")
#define CP_WAIT(N)  asm volatile("cp.async.wait_group %0;" :: "n"(N) : "memory")

__device__ __forceinline__ void ldsm4(uint32_t* r, const void* p) {
    uint32_t a = smem_u32(p);
    asm volatile("ldmatrix.sync.aligned.m8n8.x4.shared.b16 {%0,%1,%2,%3}, [%4];"
        : "=r"(r[0]), "=r"(r[1]), "=r"(r[2]), "=r"(r[3]) : "r"(a));
}
__device__ __forceinline__ void ldsm4t(uint32_t* r, const void* p) {
    uint32_t a = smem_u32(p);
    asm volatile("ldmatrix.sync.aligned.m8n8.x4.trans.shared.b16 {%0,%1,%2,%3}, [%4];"
        : "=r"(r[0]), "=r"(r[1]), "=r"(r[2]), "=r"(r[3]) : "r"(a));
}
__device__ __forceinline__ void mma16816(float* c, const uint32_t* a, const uint32_t* b) {
    asm volatile("mma.sync.aligned.m16n8k16.row.col.f32.bf16.bf16.f32 "
        "{%0,%1,%2,%3}, {%4,%5,%6,%7}, {%8,%9}, {%0,%1,%2,%3};"
        : "+f"(c[0]), "+f"(c[1]), "+f"(c[2]), "+f"(c[3])
        : "r"(a[0]), "r"(a[1]), "r"(a[2]), "r"(a[3]), "r"(b[0]), "r"(b[1]));
}

__device__ __forceinline__ float gelu_f(float v) {
    return 0.5f * v * (1.0f + erff(v * 0.70710678118654752f));
}
__device__ __forceinline__ uint32_t pack_bf2(float a, float b) {
    __nv_bfloat162 h = __float22bfloat162_rn(make_float2(a, b));
    return *reinterpret_cast<uint32_t*>(&h);
}

// ---------------------------------------------------------------------------
// bf16 mma.sync GEMM: C[n][m] = epi( sum_k A[n][k] * W[k][m] )
//   A: bf16 [Nrows][K] row-major, W: bf16 [K][M] row-major
//   Tile 128x128, BK=32, 256 thr (8 warps, 4x2), double-buffered cp.async.
//   EPI 0: bf16 out = acc + bias
//   EPI 1: bf16 out = gelu(acc + bias)
//   EPI 2: f32 out  = resid + (acc + bias) * ls
// ---------------------------------------------------------------------------
template<int EPI>
__global__ void __launch_bounds__(256, 2)
mma_gemm(const __nv_bfloat16* __restrict__ A, const __nv_bfloat16* __restrict__ W,
         const float* __restrict__ bias, void* __restrict__ Cout, int K, int M,
         const float* __restrict__ resid, const float* __restrict__ ls) {
    __shared__ __align__(16) __nv_bfloat16 As[2][128][40];   // pad 8: conflict-free ldsm
    __shared__ __align__(16) __nv_bfloat16 Bs[2][32][136];   // pad 8: conflict-free ldsm.trans

    int tid = threadIdx.x, wid = tid >> 5, lane = tid & 31;
    int wm = wid & 3, wn = wid >> 2;
    size_t rowBase = (size_t)blockIdx.y * 128;
    int colBase = blockIdx.x * 128;
    const __nv_bfloat16* Abase = A + rowBase * (size_t)K;

    auto prefetch = [&](int cc, int buf) {
        int k0 = cc << 5;
        #pragma unroll
        for (int i = 0; i < 2; i++) {
            int q = (i << 8) + tid;
            int r = q >> 2, c = (q & 3) << 3;
            cp16(&As[buf][r][c], Abase + (size_t)r * K + k0 + c);
            int r2 = q >> 4, c2 = (q & 15) << 3;
            cp16(&Bs[buf][r2][c2], W + (size_t)(k0 + r2) * M + colBase + c2);
        }
    };

    float acc[2][8][4];
    #pragma unroll
    for (int mi = 0; mi < 2; mi++)
        #pragma unroll
        for (int nj = 0; nj < 8; nj++)
            #pragma unroll
            for (int t = 0; t < 4; t++) acc[mi][nj][t] = 0.f;

    int nch = K >> 5;
    prefetch(0, 0);
    CP_COMMIT();

    int la = lane & 15, lb = lane >> 4;
    #pragma unroll 1
    for (int cc = 0; cc < nch; cc++) {
        int buf = cc & 1;
        if (cc + 1 < nch) {
            prefetch(cc + 1, buf ^ 1);
            CP_COMMIT();
            CP_WAIT(1);
        } else {
            CP_WAIT(0);
        }
        __syncthreads();

        #pragma unroll
        for (int ks = 0; ks < 2; ks++) {
            uint32_t af[2][4], bf[4][4];
            #pragma unroll
            for (int mi = 0; mi < 2; mi++)
                ldsm4(af[mi], &As[buf][wm * 32 + mi * 16 + la][ks * 16 + lb * 8]);
            #pragma unroll
            for (int ng = 0; ng < 4; ng++)
                ldsm4t(bf[ng], &Bs[buf][ks * 16 + la][wn * 64 + ng * 16 + lb * 8]);
            #pragma unroll
            for (int mi = 0; mi < 2; mi++)
                #pragma unroll
                for (int nj = 0; nj < 8; nj++)
                    mma16816(acc[mi][nj], af[mi], &bf[nj >> 1][(nj & 1) * 2]);
        }
        __syncthreads();
    }

    // ---- epilogue ----
    int tg = lane >> 2, tp = lane & 3;
    #pragma unroll
    for (int mi = 0; mi < 2; mi++) {
        size_t r0 = rowBase + (size_t)(wm * 32 + mi * 16 + tg);
        size_t r1 = r0 + 8;
        #pragma unroll
        for (int nj = 0; nj < 8; nj++) {
            int col = colBase + wn * 64 + nj * 8 + tp * 2;
            float* ac = acc[mi][nj];
            float b0 = __ldg(&bias[col]), b1 = __ldg(&bias[col + 1]);
            if (EPI == 0 || EPI == 1) {
                float v0 = ac[0] + b0, v1 = ac[1] + b1;
                float v2 = ac[2] + b0, v3 = ac[3] + b1;
                if (EPI == 1) { v0 = gelu_f(v0); v1 = gelu_f(v1); v2 = gelu_f(v2); v3 = gelu_f(v3); }
                __nv_bfloat16* op = (__nv_bfloat16*)Cout;
                *(uint32_t*)(op + r0 * M + col) = pack_bf2(v0, v1);
                *(uint32_t*)(op + r1 * M + col) = pack_bf2(v2, v3);
            } else {
                float s0 = __ldg(&ls[col]), s1 = __ldg(&ls[col + 1]);
                float* op = (float*)Cout;
                float2 rr0 = *(const float2*)(resid + r0 * M + col);
                float2 rr1 = *(const float2*)(resid + r1 * M + col);
                float2 o0 = make_float2(rr0.x + (ac[0] + b0) * s0, rr0.y + (ac[1] + b1) * s1);
                float2 o1 = make_float2(rr1.x + (ac[2] + b0) * s0, rr1.y + (ac[3] + b1) * s1);
                *(float2*)(op + r0 * M + col) = o0;
                *(float2*)(op + r1 * M + col) = o1;
            }
        }
    }
}

// ---------------------------------------------------------------------------
// LayerNorm (512) fp32 in -> bf16 out. One block (128 thr) per row.
// ---------------------------------------------------------------------------
__device__ __forceinline__ void block_reduce_2(float& s, float& sq) {
    #pragma unroll
    for (int off = 16; off > 0; off >>= 1) {
        s  += __shfl_down_sync(0xffffffffu, s,  off);
        sq += __shfl_down_sync(0xffffffffu, sq, off);
    }
    __shared__ float sh[8];
    int w = threadIdx.x >> 5, lane = threadIdx.x & 31;
    if (lane == 0) { sh[w] = s; sh[4 + w] = sq; }
    __syncthreads();
    if (threadIdx.x < 32) {
        float a = (lane < 4) ? sh[lane] : 0.f;
        float b = (lane < 4) ? sh[4 + lane] : 0.f;
        #pragma unroll
        for (int off = 2; off > 0; off >>= 1) {
            a += __shfl_down_sync(0xffffffffu, a, off);
            b += __shfl_down_sync(0xffffffffu, b, off);
        }
        if (lane == 0) { sh[0] = a; sh[1] = b; }
    }
    __syncthreads();
    s = sh[0]; sq = sh[1];
}

__global__ void ln_kernel(const float* __restrict__ x, const float* __restrict__ g,
                          const float* __restrict__ b, __nv_bfloat16* __restrict__ out) {
    size_t row = blockIdx.x;
    float4 v = ((const float4*)(x + row * DIMV))[threadIdx.x];
    float s  = v.x + v.y + v.z + v.w;
    float sq = v.x * v.x + v.y * v.y + v.z * v.z + v.w * v.w;
    block_reduce_2(s, sq);
    float mu  = s * (1.0f / DIMV);
    float var = sq * (1.0f / DIMV) - mu * mu;
    float r   = rsqrtf(var + LN_EPS);
    float4 gg = ((const float4*)g)[threadIdx.x];
    float4 bb = ((const float4*)b)[threadIdx.x];
    float o0 = (v.x - mu) * r * gg.x + bb.x;
    float o1 = (v.y - mu) * r * gg.y + bb.y;
    float o2 = (v.z - mu) * r * gg.z + bb.z;
    float o3 = (v.w - mu) * r * gg.w + bb.w;
    *(uint2*)(out + row * DIMV + threadIdx.x * 4) = make_uint2(pack_bf2(o0, o1), pack_bf2(o2, o3));
}

// ---------------------------------------------------------------------------
// Fused depthwise conv (k=3,5,7 averaged) + GELU, bf16 in/out.
// ---------------------------------------------------------------------------
__global__ void conv_gelu_kernel(const __nv_bfloat16* __restrict__ h,
                                 const float* __restrict__ w3, const float* __restrict__ b3,
                                 const float* __restrict__ w5, const float* __restrict__ b5,
                                 const float* __restrict__ w7, const float* __restrict__ b7,
                                 __nv_bfloat16* __restrict__ out) {
    size_t idx = (size_t)blockIdx.x * blockDim.x + threadIdx.x;
    int c = (int)(idx & (DIMV - 1));
    size_t n = idx >> 9;
    int l = (int)(n & (LV - 1));
    size_t bb = n >> 11;

    float taps[7];
    #pragma unroll
    for (int j = 0; j < 7; j++) taps[j] = w7[c * 7 + j];
    #pragma unroll
    for (int j = 1; j <= 5; j++) taps[j] += w5[c * 5 + (j - 1)];
    #pragma unroll
    for (int j = 2; j <= 4; j++) taps[j] += w3[c * 3 + (j - 2)];

    float acc = b3[c] + b5[c] + b7[c];
    const __nv_bfloat16* base = h + (bb * LV) * DIMV + c;
    #pragma unroll
    for (int j = 0; j < 7; j++) {
        int ll = l + j - 3;
        if (ll >= 0 && ll < LV)
            acc += taps[j] * __bfloat162float(__ldg(base + (size_t)ll * DIMV));
    }
    acc *= (1.0f / 3.0f);
    out[idx] = __float2bfloat16(gelu_f(acc));
}

// ---------------------------------------------------------------------------
// Weight converts
// ---------------------------------------------------------------------------
__global__ void conv_bf16_kernel(const float* __restrict__ in, __nv_bfloat16* __restrict__ out, int n) {
    int i = blockIdx.x * 256 + threadIdx.x;
    if (i * 4 < n) {
        float4 v = *(const float4*)(in + i * 4);
        *(uint2*)(out + i * 4) = make_uint2(pack_bf2(v.x, v.y), pack_bf2(v.z, v.w));
    }
}
__global__ void transpose_bf16_kernel(const float* __restrict__ in, __nv_bfloat16* __restrict__ out,
                                      int R, int C) {  // out[c][r] = in[r][c]
    __shared__ float t[32][33];
    int c0 = blockIdx.x * 32, r0 = blockIdx.y * 32;
    int tx = threadIdx.x, ty = threadIdx.y;
    #pragma unroll
    for (int i = 0; i < 32; i += 8)
        t[ty + i][tx] = in[(size_t)(r0 + ty + i) * C + c0 + tx];
    __syncthreads();
    #pragma unroll
    for (int i = 0; i < 32; i += 8)
        out[(size_t)(c0 + ty + i) * R + r0 + tx] = __float2bfloat16(t[tx][ty + i]);
}

// ---------------------------------------------------------------------------
// Channel token: 2-stage atomic reduction (raw sums; /L folded into gate kernel)
// ---------------------------------------------------------------------------
__global__ void zero_kernel(float* p, int n) {
    int i = blockIdx.x * 256 + threadIdx.x;
    if (i < n) p[i] = 0.f;
}
__global__ void ct_partial_kernel(const __nv_bfloat16* __restrict__ m2, float* __restrict__ ct) {
    int o  = blockIdx.x * 128 + threadIdx.x;
    int l0 = blockIdx.y * 128;
    int b  = blockIdx.z;
    const __nv_bfloat16* p = m2 + ((size_t)b * LV + l0) * DIMV + o;
    float s = 0.f;
    #pragma unroll 8
    for (int l = 0; l < 128; l++) s += __bfloat162float(__ldg(p + (size_t)l * DIMV));
    atomicAdd(&ct[b * DIMV + o], s);
}

// ---------------------------------------------------------------------------
// gate[b] = sigmoid(gelu((ct/L) @ cg_w1 + cg_b1) @ cg_w2 + cg_b2)
// ---------------------------------------------------------------------------
__global__ void gate_kernel(const float* __restrict__ ct,
                            const float* __restrict__ w1, const float* __restrict__ b1,
                            const float* __restrict__ w2, const float* __restrict__ b2,
                            float* __restrict__ gate) {
    __shared__ float sct[DIMV];
    __shared__ float shid[GHID];
    int b = blockIdx.x, t = threadIdx.x;
    for (int i = t; i < DIMV; i += 128) sct[i] = ct[b * DIMV + i] * (1.0f / LV);
    __syncthreads();
    float acc = b1[t];
    #pragma unroll 8
    for (int d = 0; d < DIMV; d++) acc += sct[d] * w1[d * GHID + t];
    shid[t] = gelu_f(acc);
    __syncthreads();
    for (int o = t; o < DIMV; o += 128) {
        float a2 = b2[o];
        #pragma unroll 8
        for (int g = 0; g < GHID; g++) a2 += shid[g] * w2[g * DIMV + o];
        gate[b * DIMV + o] = 1.0f / (1.0f + expf(-a2));
    }
}

// ---------------------------------------------------------------------------
// gated_bf[n][c] = mixed2_bf[n][c] * gate[b][c]
// ---------------------------------------------------------------------------
__global__ void gated_mul_kernel(const __nv_bfloat16* __restrict__ m2,
                                 const float* __restrict__ gate,
                                 __nv_bfloat16* __restrict__ out) {
    size_t idx = (size_t)blockIdx.x * 256 + threadIdx.x;   // per 8 bf16
    size_t e = idx * 8;
    int c = (int)(e & (DIMV - 1));
    size_t n = e >> 9;
    int b = (int)(n >> 11);
    uint4 v = *(const uint4*)(m2 + e);
    const float* gp = gate + b * DIMV + c;
    uint32_t w[4] = {v.x, v.y, v.z, v.w};
    uint4 o;
    uint32_t* ow = (uint32_t*)&o;
    #pragma unroll
    for (int i = 0; i < 4; i++) {
        __nv_bfloat162 h = *reinterpret_cast<__nv_bfloat162*>(&w[i]);
        float a = __bfloat162float(h.x) * gp[i * 2];
        float bb2 = __bfloat162float(h.y) * gp[i * 2 + 1];
        ow[i] = pack_bf2(a, bb2);
    }
    *(uint4*)(out + e) = o;
}

// ---------------------------------------------------------------------------
// launch
// ---------------------------------------------------------------------------
extern "C" void kernel_launch(void* const* d_in, const int* in_sizes, int n_in,
                              void* d_out, int out_size) {
    const float* x      = (const float*)d_in[0];
    const float* ln1_g  = (const float*)d_in[1];
    const float* ln1_b  = (const float*)d_in[2];
    const float* w3     = (const float*)d_in[3];
    const float* b3     = (const float*)d_in[4];
    const float* w5     = (const float*)d_in[5];
    const float* b5     = (const float*)d_in[6];
    const float* w7     = (const float*)d_in[7];
    const float* b7     = (const float*)d_in[8];
    const float* wmix   = (const float*)d_in[9];
    const float* bmix   = (const float*)d_in[10];
    const float* cg_w1  = (const float*)d_in[11];
    const float* cg_b1  = (const float*)d_in[12];
    const float* cg_w2  = (const float*)d_in[13];
    const float* cg_b2  = (const float*)d_in[14];
    const float* wout   = (const float*)d_in[15];
    const float* bout   = (const float*)d_in[16];
    const float* ls1    = (const float*)d_in[17];
    const float* ln2_g  = (const float*)d_in[18];
    const float* ln2_b  = (const float*)d_in[19];
    const float* ffn_w1 = (const float*)d_in[20];
    const float* ffn_b1 = (const float*)d_in[21];
    const float* ffn_w2 = (const float*)d_in[22];
    const float* ffn_b2 = (const float*)d_in[23];
    const float* ls2    = (const float*)d_in[24];
    float* out = (float*)d_out;

    __nv_bfloat16 *p_hln, *p_mixg, *p_mixed2, *p_gated, *p_h2, *p_hid;
    __nv_bfloat16 *p_wmixT, *p_wout, *p_w1, *p_w2;
    float *p_x1, *p_ct, *p_gate;
    cudaGetSymbolAddress((void**)&p_hln,    g_hln_bf);
    cudaGetSymbolAddress((void**)&p_mixg,   g_mixg_bf);
    cudaGetSymbolAddress((void**)&p_mixed2, g_mixed2_bf);
    cudaGetSymbolAddress((void**)&p_gated,  g_gated_bf);
    cudaGetSymbolAddress((void**)&p_h2,     g_h2_bf);
    cudaGetSymbolAddress((void**)&p_hid,    g_hid_bf);
    cudaGetSymbolAddress((void**)&p_x1,     g_x1);
    cudaGetSymbolAddress((void**)&p_ct,     g_ct);
    cudaGetSymbolAddress((void**)&p_gate,   g_gate);
    cudaGetSymbolAddress((void**)&p_wmixT,  g_wmixT_bf);
    cudaGetSymbolAddress((void**)&p_wout,   g_wout_bf);
    cudaGetSymbolAddress((void**)&p_w1,     g_w1_bf);
    cudaGetSymbolAddress((void**)&p_w2,     g_w2_bf);

    // weight prep: wmix^T (-> [c][o]); others straight bf16 converts ([k][m] as given)
    transpose_bf16_kernel<<<dim3(DIMV / 32, DIMV / 32), dim3(32, 8)>>>(wmix, p_wmixT, DIMV, DIMV);
    conv_bf16_kernel<<<DIMV * DIMV / 4 / 256, 256>>>(wout, p_wout, DIMV * DIMV);
    conv_bf16_kernel<<<DIMV * HIDV / 4 / 256, 256>>>(ffn_w1, p_w1, DIMV * HIDV);
    conv_bf16_kernel<<<HIDV * DIMV / 4 / 256, 256>>>(ffn_w2, p_w2, HIDV * DIMV);

    // 1) LN1 -> bf16
    ln_kernel<<<NROWS, 128>>>(x, ln1_g, ln1_b, p_hln);
    // 2) conv + gelu -> bf16
    conv_gelu_kernel<<<(NROWS * DIMV) / 256, 256>>>(p_hln, w3, b3, w5, b5, w7, b7, p_mixg);
    // 3) mixed2 = mixg @ wmixT + bmix  (bf16 out)
    mma_gemm<0><<<dim3(DIMV / 128, NROWS / 128), 256>>>(
        p_mixg, p_wmixT, bmix, p_mixed2, DIMV, DIMV, nullptr, nullptr);
    // 4) channel token
    zero_kernel<<<(BV * DIMV + 255) / 256, 256>>>(p_ct, BV * DIMV);
    ct_partial_kernel<<<dim3(DIMV / 128, LV / 128, BV), 128>>>(p_mixed2, p_ct);
    // 5) gate MLP
    gate_kernel<<<BV, 128>>>(p_ct, cg_w1, cg_b1, cg_w2, cg_b2, p_gate);
    // 6) gated = mixed2 * gate
    gated_mul_kernel<<<(NROWS * DIMV / 8) / 256, 256>>>(p_mixed2, p_gate, p_gated);
    // 7) x1 = x + (gated @ wout + bout) * ls1
    mma_gemm<2><<<dim3(DIMV / 128, NROWS / 128), 256>>>(
        p_gated, p_wout, bout, p_x1, DIMV, DIMV, x, ls1);
    // 8) LN2 -> bf16
    ln_kernel<<<NROWS, 128>>>(p_x1, ln2_g, ln2_b, p_h2);
    // 9) hid = gelu(h2 @ ffn_w1 + ffn_b1)  (bf16 out)
    mma_gemm<1><<<dim3(HIDV / 128, NROWS / 128), 256>>>(
        p_h2, p_w1, ffn_b1, p_hid, DIMV, HIDV, nullptr, nullptr);
    // 10) out = x1 + (hid @ ffn_w2 + ffn_b2) * ls2
    mma_gemm<2><<<dim3(DIMV / 128, NROWS / 128), 256>>>(
        p_hid, p_w2, ffn_b2, out, HIDV, DIMV, p_x1, ls2);
}

// round 4
// speedup vs baseline: 5.5785x; 1.0566x over previous
#include <cuda_runtime.h>
#include <cuda_bf16.h>
#include <math.h>
#include <stdint.h>

// ---------------------------------------------------------------------------
// Problem constants
// ---------------------------------------------------------------------------
#define DIMV 512
#define BV   16
#define LV   2048
#define NROWS (BV * LV)      // 32768
#define HIDV 2048
#define GHID 128
#define LN_EPS 1e-5f

// ---------------------------------------------------------------------------
// Scratch (device globals — no allocations allowed)
// ---------------------------------------------------------------------------
__device__ __nv_bfloat16 g_hln_bf   [(size_t)NROWS * DIMV];
__device__ __nv_bfloat16 g_mixg_bf  [(size_t)NROWS * DIMV];
__device__ __nv_bfloat16 g_mixed2_bf[(size_t)NROWS * DIMV];
__device__ __nv_bfloat16 g_gated_bf [(size_t)NROWS * DIMV];
__device__ __nv_bfloat16 g_h2_bf    [(size_t)NROWS * DIMV];
__device__ __nv_bfloat16 g_hid_bf   [(size_t)NROWS * HIDV];
__device__ float g_x1   [(size_t)NROWS * DIMV];
__device__ float g_ct   [BV * DIMV];
__device__ float g_gate [BV * DIMV];
__device__ __nv_bfloat16 g_wmixT_bf[DIMV * DIMV];          // [c][o]  (wmix.T)
__device__ __nv_bfloat16 g_wout_bf [DIMV * DIMV];          // [k][m] as given
__device__ __nv_bfloat16 g_w1_bf   [(size_t)DIMV * HIDV];  // [k][m] as given
__device__ __nv_bfloat16 g_w2_bf   [(size_t)HIDV * DIMV];  // [k][m] as given

// ---------------------------------------------------------------------------
// Helpers
// ---------------------------------------------------------------------------
__device__ __forceinline__ uint32_t smem_u32(const void* p) {
    uint32_t a;
    asm("{ .reg .u64 t; cvta.to.shared.u64 t, %1; cvt.u32.u64 %0, t; }" : "=r"(a) : "l"(p));
    return a;
}
__device__ __forceinline__ void cp16(void* sdst, const void* gsrc) {
    uint32_t s = smem_u32(sdst);
    asm volatile("cp.async.cg.shared.global [%0], [%1], 16;" :: "r"(s), "l"(gsrc));
}
#define CP_COMMIT() asm volatile("cp.async.commit_group;" ::: "memory")
#define CP_WAIT(N)  asm volatile("cp.async.wait_group %0;" :: "n"(N) : "memory")

__device__ __forceinline__ void ldsm4(uint32_t* r, const void* p) {
    uint32_t a = smem_u32(p);
    asm volatile("ldmatrix.sync.aligned.m8n8.x4.shared.b16 {%0,%1,%2,%3}, [%4];"
        : "=r"(r[0]), "=r"(r[1]), "=r"(r[2]), "=r"(r[3]) : "r"(a));
}
__device__ __forceinline__ void ldsm4t(uint32_t* r, const void* p) {
    uint32_t a = smem_u32(p);
    asm volatile("ldmatrix.sync.aligned.m8n8.x4.trans.shared.b16 {%0,%1,%2,%3}, [%4];"
        : "=r"(r[0]), "=r"(r[1]), "=r"(r[2]), "=r"(r[3]) : "r"(a));
}
__device__ __forceinline__ void mma16816(float* c, const uint32_t* a, const uint32_t* b) {
    asm volatile("mma.sync.aligned.m16n8k16.row.col.f32.bf16.bf16.f32 "
        "{%0,%1,%2,%3}, {%4,%5,%6,%7}, {%8,%9}, {%0,%1,%2,%3};"
        : "+f"(c[0]), "+f"(c[1]), "+f"(c[2]), "+f"(c[3])
        : "r"(a[0]), "r"(a[1]), "r"(a[2]), "r"(a[3]), "r"(b[0]), "r"(b[1]));
}

__device__ __forceinline__ float gelu_f(float v) {
    return 0.5f * v * (1.0f + erff(v * 0.70710678118654752f));
}
__device__ __forceinline__ uint32_t pack_bf2(float a, float b) {
    __nv_bfloat162 h = __float22bfloat162_rn(make_float2(a, b));
    return *reinterpret_cast<uint32_t*>(&h);
}

// ---------------------------------------------------------------------------
// bf16 mma.sync GEMM: C[n][m] = epi( sum_k A[n][k] * W[k][m] )
//   A: bf16 [Nrows][K] row-major, W: bf16 [K][M] row-major
//   Tile 128x128, BK=32, 256 thr (8 warps, 4x2).
//   3-stage cp.async pipeline (prefetch distance 2), ONE __syncthreads/iter.
//   EPI 0: bf16 out = acc + bias
//   EPI 1: bf16 out = gelu(acc + bias)
//   EPI 2: f32 out  = resid + (acc + bias) * ls
// ---------------------------------------------------------------------------
#define AS_STRIDE 40            // 128 rows x 40 bf16 (pad 8)
#define BS_STRIDE 136           // 32 rows x 136 bf16 (pad 8)
#define AS_STAGE  (128 * AS_STRIDE)   // 5120 bf16
#define BS_STAGE  (32 * BS_STRIDE)    // 4352 bf16
#define GEMM_SMEM ((3 * (AS_STAGE + BS_STAGE)) * 2)   // 56832 bytes

template<int EPI>
__global__ void __launch_bounds__(256, 2)
mma_gemm(const __nv_bfloat16* __restrict__ A, const __nv_bfloat16* __restrict__ W,
         const float* __restrict__ bias, void* __restrict__ Cout, int K, int M,
         const float* __restrict__ resid, const float* __restrict__ ls) {
    extern __shared__ __nv_bfloat16 sm[];
    __nv_bfloat16* As = sm;                 // [3][128][40]
    __nv_bfloat16* Bs = sm + 3 * AS_STAGE;  // [3][32][136]

    int tid = threadIdx.x, wid = tid >> 5, lane = tid & 31;
    int wm = wid & 3, wn = wid >> 2;
    size_t rowBase = (size_t)blockIdx.y * 128;
    int colBase = blockIdx.x * 128;
    const __nv_bfloat16* Abase = A + rowBase * (size_t)K;

    auto prefetch = [&](int cc, int st) {
        int k0 = cc << 5;
        __nv_bfloat16* as = As + st * AS_STAGE;
        __nv_bfloat16* bs = Bs + st * BS_STAGE;
        #pragma unroll
        for (int i = 0; i < 2; i++) {
            int q = (i << 8) + tid;
            int r = q >> 2, c = (q & 3) << 3;
            cp16(as + r * AS_STRIDE + c, Abase + (size_t)r * K + k0 + c);
            int r2 = q >> 4, c2 = (q & 15) << 3;
            cp16(bs + r2 * BS_STRIDE + c2, W + (size_t)(k0 + r2) * M + colBase + c2);
        }
    };

    float acc[2][8][4];
    #pragma unroll
    for (int mi = 0; mi < 2; mi++)
        #pragma unroll
        for (int nj = 0; nj < 8; nj++)
            #pragma unroll
            for (int t = 0; t < 4; t++) acc[mi][nj][t] = 0.f;

    int nch = K >> 5;
    prefetch(0, 0); CP_COMMIT();
    prefetch(1, 1); CP_COMMIT();

    int la = lane & 15, lb = lane >> 4;
    int st = 0;          // stage of current chunk
    int stw = 2;         // stage to write next prefetch into
    #pragma unroll 1
    for (int cc = 0; cc < nch; cc++) {
        CP_WAIT(1);
        __syncthreads();
        if (cc + 2 < nch) prefetch(cc + 2, stw);
        CP_COMMIT();

        __nv_bfloat16* as = As + st * AS_STAGE;
        __nv_bfloat16* bs = Bs + st * BS_STAGE;
        #pragma unroll
        for (int ks = 0; ks < 2; ks++) {
            uint32_t af[2][4], bf[4][4];
            #pragma unroll
            for (int mi = 0; mi < 2; mi++)
                ldsm4(af[mi], as + (wm * 32 + mi * 16 + la) * AS_STRIDE + ks * 16 + lb * 8);
            #pragma unroll
            for (int ng = 0; ng < 4; ng++)
                ldsm4t(bf[ng], bs + (ks * 16 + la) * BS_STRIDE + wn * 64 + ng * 16 + lb * 8);
            #pragma unroll
            for (int mi = 0; mi < 2; mi++)
                #pragma unroll
                for (int nj = 0; nj < 8; nj++)
                    mma16816(acc[mi][nj], af[mi], &bf[nj >> 1][(nj & 1) * 2]);
        }
        st = (st == 2) ? 0 : st + 1;
        stw = (stw == 2) ? 0 : stw + 1;
    }

    // ---- epilogue ----
    int tg = lane >> 2, tp = lane & 3;
    #pragma unroll
    for (int mi = 0; mi < 2; mi++) {
        size_t r0 = rowBase + (size_t)(wm * 32 + mi * 16 + tg);
        size_t r1 = r0 + 8;
        #pragma unroll
        for (int nj = 0; nj < 8; nj++) {
            int col = colBase + wn * 64 + nj * 8 + tp * 2;
            float* ac = acc[mi][nj];
            float b0 = __ldg(&bias[col]), b1 = __ldg(&bias[col + 1]);
            if (EPI == 0 || EPI == 1) {
                float v0 = ac[0] + b0, v1 = ac[1] + b1;
                float v2 = ac[2] + b0, v3 = ac[3] + b1;
                if (EPI == 1) { v0 = gelu_f(v0); v1 = gelu_f(v1); v2 = gelu_f(v2); v3 = gelu_f(v3); }
                __nv_bfloat16* op = (__nv_bfloat16*)Cout;
                *(uint32_t*)(op + r0 * M + col) = pack_bf2(v0, v1);
                *(uint32_t*)(op + r1 * M + col) = pack_bf2(v2, v3);
            } else {
                float s0 = __ldg(&ls[col]), s1 = __ldg(&ls[col + 1]);
                float* op = (float*)Cout;
                float2 rr0 = *(const float2*)(resid + r0 * M + col);
                float2 rr1 = *(const float2*)(resid + r1 * M + col);
                float2 o0 = make_float2(rr0.x + (ac[0] + b0) * s0, rr0.y + (ac[1] + b1) * s1);
                float2 o1 = make_float2(rr1.x + (ac[2] + b0) * s0, rr1.y + (ac[3] + b1) * s1);
                *(float2*)(op + r0 * M + col) = o0;
                *(float2*)(op + r1 * M + col) = o1;
            }
        }
    }
}

// ---------------------------------------------------------------------------
// LayerNorm (512) fp32 in -> bf16 out. One block (128 thr) per row.
// ---------------------------------------------------------------------------
__device__ __forceinline__ void block_reduce_2(float& s, float& sq) {
    #pragma unroll
    for (int off = 16; off > 0; off >>= 1) {
        s  += __shfl_down_sync(0xffffffffu, s,  off);
        sq += __shfl_down_sync(0xffffffffu, sq, off);
    }
    __shared__ float sh[8];
    int w = threadIdx.x >> 5, lane = threadIdx.x & 31;
    if (lane == 0) { sh[w] = s; sh[4 + w] = sq; }
    __syncthreads();
    if (threadIdx.x < 32) {
        float a = (lane < 4) ? sh[lane] : 0.f;
        float b = (lane < 4) ? sh[4 + lane] : 0.f;
        #pragma unroll
        for (int off = 2; off > 0; off >>= 1) {
            a += __shfl_down_sync(0xffffffffu, a, off);
            b += __shfl_down_sync(0xffffffffu, b, off);
        }
        if (lane == 0) { sh[0] = a; sh[1] = b; }
    }
    __syncthreads();
    s = sh[0]; sq = sh[1];
}

__global__ void ln_kernel(const float* __restrict__ x, const float* __restrict__ g,
                          const float* __restrict__ b, __nv_bfloat16* __restrict__ out) {
    size_t row = blockIdx.x;
    float4 v = ((const float4*)(x + row * DIMV))[threadIdx.x];
    float s  = v.x + v.y + v.z + v.w;
    float sq = v.x * v.x + v.y * v.y + v.z * v.z + v.w * v.w;
    block_reduce_2(s, sq);
    float mu  = s * (1.0f / DIMV);
    float var = sq * (1.0f / DIMV) - mu * mu;
    float r   = rsqrtf(var + LN_EPS);
    float4 gg = ((const float4*)g)[threadIdx.x];
    float4 bb = ((const float4*)b)[threadIdx.x];
    float o0 = (v.x - mu) * r * gg.x + bb.x;
    float o1 = (v.y - mu) * r * gg.y + bb.y;
    float o2 = (v.z - mu) * r * gg.z + bb.z;
    float o3 = (v.w - mu) * r * gg.w + bb.w;
    *(uint2*)(out + row * DIMV + threadIdx.x * 4) = make_uint2(pack_bf2(o0, o1), pack_bf2(o2, o3));
}

// ---------------------------------------------------------------------------
// Fused depthwise conv (k=3,5,7 averaged) + GELU, bf16 in/out.
// ---------------------------------------------------------------------------
__global__ void conv_gelu_kernel(const __nv_bfloat16* __restrict__ h,
                                 const float* __restrict__ w3, const float* __restrict__ b3,
                                 const float* __restrict__ w5, const float* __restrict__ b5,
                                 const float* __restrict__ w7, const float* __restrict__ b7,
                                 __nv_bfloat16* __restrict__ out) {
    size_t idx = (size_t)blockIdx.x * blockDim.x + threadIdx.x;
    int c = (int)(idx & (DIMV - 1));
    size_t n = idx >> 9;
    int l = (int)(n & (LV - 1));
    size_t bb = n >> 11;

    float taps[7];
    #pragma unroll
    for (int j = 0; j < 7; j++) taps[j] = w7[c * 7 + j];
    #pragma unroll
    for (int j = 1; j <= 5; j++) taps[j] += w5[c * 5 + (j - 1)];
    #pragma unroll
    for (int j = 2; j <= 4; j++) taps[j] += w3[c * 3 + (j - 2)];

    float acc = b3[c] + b5[c] + b7[c];
    const __nv_bfloat16* base = h + (bb * LV) * DIMV + c;
    #pragma unroll
    for (int j = 0; j < 7; j++) {
        int ll = l + j - 3;
        if (ll >= 0 && ll < LV)
            acc += taps[j] * __bfloat162float(__ldg(base + (size_t)ll * DIMV));
    }
    acc *= (1.0f / 3.0f);
    out[idx] = __float2bfloat16(gelu_f(acc));
}

// ---------------------------------------------------------------------------
// Weight converts
// ---------------------------------------------------------------------------
__global__ void conv_bf16_kernel(const float* __restrict__ in, __nv_bfloat16* __restrict__ out, int n) {
    int i = blockIdx.x * 256 + threadIdx.x;
    if (i * 4 < n) {
        float4 v = *(const float4*)(in + i * 4);
        *(uint2*)(out + i * 4) = make_uint2(pack_bf2(v.x, v.y), pack_bf2(v.z, v.w));
    }
}
__global__ void transpose_bf16_kernel(const float* __restrict__ in, __nv_bfloat16* __restrict__ out,
                                      int R, int C) {  // out[c][r] = in[r][c]
    __shared__ float t[32][33];
    int c0 = blockIdx.x * 32, r0 = blockIdx.y * 32;
    int tx = threadIdx.x, ty = threadIdx.y;
    #pragma unroll
    for (int i = 0; i < 32; i += 8)
        t[ty + i][tx] = in[(size_t)(r0 + ty + i) * C + c0 + tx];
    __syncthreads();
    #pragma unroll
    for (int i = 0; i < 32; i += 8)
        out[(size_t)(c0 + ty + i) * R + r0 + tx] = __float2bfloat16(t[tx][ty + i]);
}

// ---------------------------------------------------------------------------
// Channel token: 2-stage atomic reduction (raw sums; /L folded into gate kernel)
// ---------------------------------------------------------------------------
__global__ void zero_kernel(float* p, int n) {
    int i = blockIdx.x * 256 + threadIdx.x;
    if (i < n) p[i] = 0.f;
}
__global__ void ct_partial_kernel(const __nv_bfloat16* __restrict__ m2, float* __restrict__ ct) {
    int o  = blockIdx.x * 128 + threadIdx.x;
    int l0 = blockIdx.y * 128;
    int b  = blockIdx.z;
    const __nv_bfloat16* p = m2 + ((size_t)b * LV + l0) * DIMV + o;
    float s = 0.f;
    #pragma unroll 8
    for (int l = 0; l < 128; l++) s += __bfloat162float(__ldg(p + (size_t)l * DIMV));
    atomicAdd(&ct[b * DIMV + o], s);
}

// ---------------------------------------------------------------------------
// gate[b] = sigmoid(gelu((ct/L) @ cg_w1 + cg_b1) @ cg_w2 + cg_b2)
// ---------------------------------------------------------------------------
__global__ void gate_kernel(const float* __restrict__ ct,
                            const float* __restrict__ w1, const float* __restrict__ b1,
                            const float* __restrict__ w2, const float* __restrict__ b2,
                            float* __restrict__ gate) {
    __shared__ float sct[DIMV];
    __shared__ float shid[GHID];
    int b = blockIdx.x, t = threadIdx.x;
    for (int i = t; i < DIMV; i += 128) sct[i] = ct[b * DIMV + i] * (1.0f / LV);
    __syncthreads();
    float acc = b1[t];
    #pragma unroll 8
    for (int d = 0; d < DIMV; d++) acc += sct[d] * w1[d * GHID + t];
    shid[t] = gelu_f(acc);
    __syncthreads();
    for (int o = t; o < DIMV; o += 128) {
        float a2 = b2[o];
        #pragma unroll 8
        for (int g = 0; g < GHID; g++) a2 += shid[g] * w2[g * DIMV + o];
        gate[b * DIMV + o] = 1.0f / (1.0f + expf(-a2));
    }
}

// ---------------------------------------------------------------------------
// gated_bf[n][c] = mixed2_bf[n][c] * gate[b][c]
// ---------------------------------------------------------------------------
__global__ void gated_mul_kernel(const __nv_bfloat16* __restrict__ m2,
                                 const float* __restrict__ gate,
                                 __nv_bfloat16* __restrict__ out) {
    size_t idx = (size_t)blockIdx.x * 256 + threadIdx.x;   // per 8 bf16
    size_t e = idx * 8;
    int c = (int)(e & (DIMV - 1));
    size_t n = e >> 9;
    int b = (int)(n >> 11);
    uint4 v = *(const uint4*)(m2 + e);
    const float* gp = gate + b * DIMV + c;
    uint32_t w[4] = {v.x, v.y, v.z, v.w};
    uint4 o;
    uint32_t* ow = (uint32_t*)&o;
    #pragma unroll
    for (int i = 0; i < 4; i++) {
        __nv_bfloat162 h = *reinterpret_cast<__nv_bfloat162*>(&w[i]);
        float a = __bfloat162float(h.x) * gp[i * 2];
        float bb2 = __bfloat162float(h.y) * gp[i * 2 + 1];
        ow[i] = pack_bf2(a, bb2);
    }
    *(uint4*)(out + e) = o;
}

// ---------------------------------------------------------------------------
// launch
// ---------------------------------------------------------------------------
extern "C" void kernel_launch(void* const* d_in, const int* in_sizes, int n_in,
                              void* d_out, int out_size) {
    const float* x      = (const float*)d_in[0];
    const float* ln1_g  = (const float*)d_in[1];
    const float* ln1_b  = (const float*)d_in[2];
    const float* w3     = (const float*)d_in[3];
    const float* b3     = (const float*)d_in[4];
    const float* w5     = (const float*)d_in[5];
    const float* b5     = (const float*)d_in[6];
    const float* w7     = (const float*)d_in[7];
    const float* b7     = (const float*)d_in[8];
    const float* wmix   = (const float*)d_in[9];
    const float* bmix   = (const float*)d_in[10];
    const float* cg_w1  = (const float*)d_in[11];
    const float* cg_b1  = (const float*)d_in[12];
    const float* cg_w2  = (const float*)d_in[13];
    const float* cg_b2  = (const float*)d_in[14];
    const float* wout   = (const float*)d_in[15];
    const float* bout   = (const float*)d_in[16];
    const float* ls1    = (const float*)d_in[17];
    const float* ln2_g  = (const float*)d_in[18];
    const float* ln2_b  = (const float*)d_in[19];
    const float* ffn_w1 = (const float*)d_in[20];
    const float* ffn_b1 = (const float*)d_in[21];
    const float* ffn_w2 = (const float*)d_in[22];
    const float* ffn_b2 = (const float*)d_in[23];
    const float* ls2    = (const float*)d_in[24];
    float* out = (float*)d_out;

    __nv_bfloat16 *p_hln, *p_mixg, *p_mixed2, *p_gated, *p_h2, *p_hid;
    __nv_bfloat16 *p_wmixT, *p_wout, *p_w1, *p_w2;
    float *p_x1, *p_ct, *p_gate;
    cudaGetSymbolAddress((void**)&p_hln,    g_hln_bf);
    cudaGetSymbolAddress((void**)&p_mixg,   g_mixg_bf);
    cudaGetSymbolAddress((void**)&p_mixed2, g_mixed2_bf);
    cudaGetSymbolAddress((void**)&p_gated,  g_gated_bf);
    cudaGetSymbolAddress((void**)&p_h2,     g_h2_bf);
    cudaGetSymbolAddress((void**)&p_hid,    g_hid_bf);
    cudaGetSymbolAddress((void**)&p_x1,     g_x1);
    cudaGetSymbolAddress((void**)&p_ct,     g_ct);
    cudaGetSymbolAddress((void**)&p_gate,   g_gate);
    cudaGetSymbolAddress((void**)&p_wmixT,  g_wmixT_bf);
    cudaGetSymbolAddress((void**)&p_wout,   g_wout_bf);
    cudaGetSymbolAddress((void**)&p_w1,     g_w1_bf);
    cudaGetSymbolAddress((void**)&p_w2,     g_w2_bf);

    cudaFuncSetAttribute(mma_gemm<0>, cudaFuncAttributeMaxDynamicSharedMemorySize, GEMM_SMEM);
    cudaFuncSetAttribute(mma_gemm<1>, cudaFuncAttributeMaxDynamicSharedMemorySize, GEMM_SMEM);
    cudaFuncSetAttribute(mma_gemm<2>, cudaFuncAttributeMaxDynamicSharedMemorySize, GEMM_SMEM);

    // weight prep: wmix^T (-> [c][o]); others straight bf16 converts ([k][m] as given)
    transpose_bf16_kernel<<<dim3(DIMV / 32, DIMV / 32), dim3(32, 8)>>>(wmix, p_wmixT, DIMV, DIMV);
    conv_bf16_kernel<<<DIMV * DIMV / 4 / 256, 256>>>(wout, p_wout, DIMV * DIMV);
    conv_bf16_kernel<<<DIMV * HIDV / 4 / 256, 256>>>(ffn_w1, p_w1, DIMV * HIDV);
    conv_bf16_kernel<<<HIDV * DIMV / 4 / 256, 256>>>(ffn_w2, p_w2, HIDV * DIMV);

    // 1) LN1 -> bf16
    ln_kernel<<<NROWS, 128>>>(x, ln1_g, ln1_b, p_hln);
    // 2) conv + gelu -> bf16
    conv_gelu_kernel<<<(NROWS * DIMV) / 256, 256>>>(p_hln, w3, b3, w5, b5, w7, b7, p_mixg);
    // 3) mixed2 = mixg @ wmixT + bmix  (bf16 out)
    mma_gemm<0><<<dim3(DIMV / 128, NROWS / 128), 256, GEMM_SMEM>>>(
        p_mixg, p_wmixT, bmix, p_mixed2, DIMV, DIMV, nullptr, nullptr);
    // 4) channel token
    zero_kernel<<<(BV * DIMV + 255) / 256, 256>>>(p_ct, BV * DIMV);
    ct_partial_kernel<<<dim3(DIMV / 128, LV / 128, BV), 128>>>(p_mixed2, p_ct);
    // 5) gate MLP
    gate_kernel<<<BV, 128>>>(p_ct, cg_w1, cg_b1, cg_w2, cg_b2, p_gate);
    // 6) gated = mixed2 * gate
    gated_mul_kernel<<<(NROWS * DIMV / 8) / 256, 256>>>(p_mixed2, p_gate, p_gated);
    // 7) x1 = x + (gated @ wout + bout) * ls1
    mma_gemm<2><<<dim3(DIMV / 128, NROWS / 128), 256, GEMM_SMEM>>>(
        p_gated, p_wout, bout, p_x1, DIMV, DIMV, x, ls1);
    // 8) LN2 -> bf16
    ln_kernel<<<NROWS, 128>>>(p_x1, ln2_g, ln2_b, p_h2);
    // 9) hid = gelu(h2 @ ffn_w1 + ffn_b1)  (bf16 out)
    mma_gemm<1><<<dim3(HIDV / 128, NROWS / 128), 256, GEMM_SMEM>>>(
        p_h2, p_w1, ffn_b1, p_hid, DIMV, HIDV, nullptr, nullptr);
    // 10) out = x1 + (hid @ ffn_w2 + ffn_b2) * ls2
    mma_gemm<2><<<dim3(DIMV / 128, NROWS / 128), 256, GEMM_SMEM>>>(
        p_hid, p_w2, ffn_b2, out, HIDV, DIMV, p_x1, ls2);
}